// round 1
// baseline (speedup 1.0000x reference)
#include <cuda_runtime.h>

#define D_MODEL 1024
#define SEQLEN  2048
#define BATCH   4
#define NHEADS  16
#define HDIM    64
#define MROWS   (BATCH * SEQLEN)   /* 8192 */
#define INV_TAU (1.0f / 0.07f)

// Scratch (allocation-free rule: __device__ globals)
__device__ float g_Qp[MROWS * D_MODEL];
__device__ float g_Kp[MROWS * D_MODEL];
__device__ float g_Vp[MROWS * D_MODEL];
__device__ float g_Ao[MROWS * D_MODEL];

// ---------------------------------------------------------------------------
// GEMM: C[M,N] = A[M,K] @ W[N,K]^T + bias[N]
// 128x128 tile, BK=8, 256 threads, 8x8 per thread.
// ---------------------------------------------------------------------------
__global__ __launch_bounds__(256) void gemm_bias_kernel(
    const float* __restrict__ A, const float* __restrict__ W,
    const float* __restrict__ bias, float* __restrict__ C,
    int M, int N, int K)
{
    __shared__ float As[8][128];
    __shared__ float Bs[8][128];

    const int tid  = threadIdx.x;
    const int brow = blockIdx.y * 128;
    const int bcol = blockIdx.x * 128;
    const int ty   = tid >> 4;          // 0..15
    const int tx   = tid & 15;          // 0..15
    const int lrow = tid >> 1;          // 0..127
    const int lk4  = (tid & 1) * 4;     // 0 or 4

    const float* Ap = A + (size_t)(brow + lrow) * K + lk4;
    const float* Wp = W + (size_t)(bcol + lrow) * K + lk4;

    float acc[8][8];
#pragma unroll
    for (int i = 0; i < 8; i++)
#pragma unroll
        for (int j = 0; j < 8; j++) acc[i][j] = 0.f;

    for (int k0 = 0; k0 < K; k0 += 8) {
        float4 av = *(const float4*)(Ap + k0);
        float4 wv = *(const float4*)(Wp + k0);
        __syncthreads();
        As[lk4 + 0][lrow] = av.x; As[lk4 + 1][lrow] = av.y;
        As[lk4 + 2][lrow] = av.z; As[lk4 + 3][lrow] = av.w;
        Bs[lk4 + 0][lrow] = wv.x; Bs[lk4 + 1][lrow] = wv.y;
        Bs[lk4 + 2][lrow] = wv.z; Bs[lk4 + 3][lrow] = wv.w;
        __syncthreads();
#pragma unroll
        for (int kk = 0; kk < 8; kk++) {
            float a[8], b[8];
            *(float4*)&a[0] = *(const float4*)&As[kk][ty * 8];
            *(float4*)&a[4] = *(const float4*)&As[kk][ty * 8 + 4];
            *(float4*)&b[0] = *(const float4*)&Bs[kk][tx * 8];
            *(float4*)&b[4] = *(const float4*)&Bs[kk][tx * 8 + 4];
#pragma unroll
            for (int i = 0; i < 8; i++)
#pragma unroll
                for (int j = 0; j < 8; j++)
                    acc[i][j] += a[i] * b[j];
        }
    }

    float bv[8];
    *(float4*)&bv[0] = *(const float4*)(bias + bcol + tx * 8);
    *(float4*)&bv[4] = *(const float4*)(bias + bcol + tx * 8 + 4);
#pragma unroll
    for (int i = 0; i < 8; i++) {
        float* Cp = C + (size_t)(brow + ty * 8 + i) * N + bcol + tx * 8;
        float4 o0 = make_float4(acc[i][0] + bv[0], acc[i][1] + bv[1],
                                acc[i][2] + bv[2], acc[i][3] + bv[3]);
        float4 o1 = make_float4(acc[i][4] + bv[4], acc[i][5] + bv[5],
                                acc[i][6] + bv[6], acc[i][7] + bv[7]);
        *(float4*)Cp       = o0;
        *(float4*)(Cp + 4) = o1;
    }
}

// ---------------------------------------------------------------------------
// Per-head L2 normalize: each warp handles one 64-element chunk.
// matches ref: x / max(sqrt(sum x^2), 1e-12)
// ---------------------------------------------------------------------------
__global__ __launch_bounds__(256) void l2norm_kernel(float* __restrict__ X, int nchunks)
{
    int gid  = blockIdx.x * blockDim.x + threadIdx.x;
    int warp = gid >> 5;
    int lane = gid & 31;
    if (warp >= nchunks) return;
    float* p = X + (size_t)warp * 64 + lane * 2;
    float2 v = *(float2*)p;
    float ss = v.x * v.x + v.y * v.y;
#pragma unroll
    for (int m = 16; m > 0; m >>= 1)
        ss += __shfl_xor_sync(0xffffffffu, ss, m);
    float inv = 1.0f / fmaxf(sqrtf(ss), 1e-12f);
    v.x *= inv; v.y *= inv;
    *(float2*)p = v;
}

// ---------------------------------------------------------------------------
// Flash attention: grid (L/64, B*H), 256 threads.
// 64x64 tiles, 4x4 per thread, online softmax.
// Layout in scratch: [B, L, D] with head h occupying cols [h*64, h*64+64).
// ---------------------------------------------------------------------------
__global__ __launch_bounds__(256) void attn_kernel(
    const float* __restrict__ Q, const float* __restrict__ K,
    const float* __restrict__ V, float* __restrict__ O)
{
    __shared__ float  Qs[64 * 64];      // [m][d], plain (broadcast reads)
    __shared__ float  KPs[64 * 65];     // K tile [n][d] stride 65; reused as P [m][k]
    __shared__ float4 Vs[64 * 16];      // [k][c4], XOR-swizzled float4 columns

    const int tid = threadIdx.x;
    const int qt  = blockIdx.x;
    const int bh  = blockIdx.y;
    const int b   = bh >> 4, h = bh & 15;
    const int base = (b * SEQLEN) * D_MODEL + h * HDIM;
    const int ty = tid >> 4, tx = tid & 15;
    const int r0 = ty * 4;
    const int n0 = tx * 4;

    // Load Q tile, pre-scaled by 1/tau
#pragma unroll
    for (int i = 0; i < 4; i++) {
        int idx = tid + i * 256;
        int r = idx >> 4, c = idx & 15;
        float4 v = *(const float4*)(Q + base + (qt * 64 + r) * D_MODEL + c * 4);
        Qs[r * 64 + c * 4 + 0] = v.x * INV_TAU;
        Qs[r * 64 + c * 4 + 1] = v.y * INV_TAU;
        Qs[r * 64 + c * 4 + 2] = v.z * INV_TAU;
        Qs[r * 64 + c * 4 + 3] = v.w * INV_TAU;
    }

    float  m_i[4], l_i[4];
    float4 o4[4];
#pragma unroll
    for (int i = 0; i < 4; i++) {
        m_i[i] = -1e30f;
        l_i[i] = 0.f;
        o4[i]  = make_float4(0.f, 0.f, 0.f, 0.f);
    }

    for (int kt = 0; kt < SEQLEN / 64; kt++) {
        __syncthreads();   // protect smem from previous iteration's readers
#pragma unroll
        for (int i = 0; i < 4; i++) {
            int idx = tid + i * 256;
            int r = idx >> 4, c = idx & 15;
            float4 kv = *(const float4*)(K + base + (kt * 64 + r) * D_MODEL + c * 4);
            KPs[r * 65 + c * 4 + 0] = kv.x;
            KPs[r * 65 + c * 4 + 1] = kv.y;
            KPs[r * 65 + c * 4 + 2] = kv.z;
            KPs[r * 65 + c * 4 + 3] = kv.w;
            float4 vv = *(const float4*)(V + base + (kt * 64 + r) * D_MODEL + c * 4);
            Vs[r * 16 + (c ^ (r & 15))] = vv;
        }
        __syncthreads();

        // S = (Q/tau) @ K^T : 4x4 per thread
        float s[4][4];
#pragma unroll
        for (int i = 0; i < 4; i++)
#pragma unroll
            for (int j = 0; j < 4; j++) s[i][j] = 0.f;

#pragma unroll
        for (int d = 0; d < 64; d++) {
            float qv[4], kv[4];
#pragma unroll
            for (int i = 0; i < 4; i++) qv[i] = Qs[(r0 + i) * 64 + d];
#pragma unroll
            for (int j = 0; j < 4; j++) kv[j] = KPs[(n0 + j) * 65 + d];
#pragma unroll
            for (int i = 0; i < 4; i++)
#pragma unroll
                for (int j = 0; j < 4; j++)
                    s[i][j] += qv[i] * kv[j];
        }
        __syncthreads();   // all K reads complete before P overwrites the buffer

        // Online softmax update; write P into KPs
#pragma unroll
        for (int i = 0; i < 4; i++) {
            float rmax = fmaxf(fmaxf(s[i][0], s[i][1]), fmaxf(s[i][2], s[i][3]));
            rmax = fmaxf(rmax, __shfl_xor_sync(0xffffffffu, rmax, 1));
            rmax = fmaxf(rmax, __shfl_xor_sync(0xffffffffu, rmax, 2));
            rmax = fmaxf(rmax, __shfl_xor_sync(0xffffffffu, rmax, 4));
            rmax = fmaxf(rmax, __shfl_xor_sync(0xffffffffu, rmax, 8));
            float mn = fmaxf(m_i[i], rmax);
            float p0 = __expf(s[i][0] - mn);
            float p1 = __expf(s[i][1] - mn);
            float p2 = __expf(s[i][2] - mn);
            float p3 = __expf(s[i][3] - mn);
            float rs = p0 + p1 + p2 + p3;
            rs += __shfl_xor_sync(0xffffffffu, rs, 1);
            rs += __shfl_xor_sync(0xffffffffu, rs, 2);
            rs += __shfl_xor_sync(0xffffffffu, rs, 4);
            rs += __shfl_xor_sync(0xffffffffu, rs, 8);
            float sc = __expf(m_i[i] - mn);
            l_i[i] = l_i[i] * sc + rs;
            m_i[i] = mn;
            o4[i].x *= sc; o4[i].y *= sc; o4[i].z *= sc; o4[i].w *= sc;
            KPs[(r0 + i) * 65 + n0 + 0] = p0;
            KPs[(r0 + i) * 65 + n0 + 1] = p1;
            KPs[(r0 + i) * 65 + n0 + 2] = p2;
            KPs[(r0 + i) * 65 + n0 + 3] = p3;
        }
        __syncthreads();

        // O += P @ V
#pragma unroll 4
        for (int k = 0; k < 64; k++) {
            float4 v4 = Vs[k * 16 + (tx ^ (k & 15))];
            float p0 = KPs[(r0 + 0) * 65 + k];
            float p1 = KPs[(r0 + 1) * 65 + k];
            float p2 = KPs[(r0 + 2) * 65 + k];
            float p3 = KPs[(r0 + 3) * 65 + k];
            o4[0].x += p0 * v4.x; o4[0].y += p0 * v4.y; o4[0].z += p0 * v4.z; o4[0].w += p0 * v4.w;
            o4[1].x += p1 * v4.x; o4[1].y += p1 * v4.y; o4[1].z += p1 * v4.z; o4[1].w += p1 * v4.w;
            o4[2].x += p2 * v4.x; o4[2].y += p2 * v4.y; o4[2].z += p2 * v4.z; o4[2].w += p2 * v4.w;
            o4[3].x += p3 * v4.x; o4[3].y += p3 * v4.y; o4[3].z += p3 * v4.z; o4[3].w += p3 * v4.w;
        }
    }

#pragma unroll
    for (int i = 0; i < 4; i++) {
        float inv = 1.0f / l_i[i];
        float4 r = make_float4(o4[i].x * inv, o4[i].y * inv, o4[i].z * inv, o4[i].w * inv);
        *(float4*)(O + base + (qt * 64 + r0 + i) * D_MODEL + tx * 4) = r;
    }
}

// ---------------------------------------------------------------------------
extern "C" void kernel_launch(void* const* d_in, const int* in_sizes, int n_in,
                              void* d_out, int out_size)
{
    const float* q  = (const float*)d_in[0];
    const float* k  = (const float*)d_in[1];
    const float* v  = (const float*)d_in[2];
    const float* Wq = (const float*)d_in[3];
    const float* bq = (const float*)d_in[4];
    const float* Wk = (const float*)d_in[5];
    const float* bk = (const float*)d_in[6];
    const float* Wv = (const float*)d_in[7];
    const float* bv = (const float*)d_in[8];
    const float* Wo = (const float*)d_in[9];
    const float* bo = (const float*)d_in[10];
    float* out = (float*)d_out;

    float *Qp, *Kp, *Vp, *Ao;
    cudaGetSymbolAddress((void**)&Qp, g_Qp);
    cudaGetSymbolAddress((void**)&Kp, g_Kp);
    cudaGetSymbolAddress((void**)&Vp, g_Vp);
    cudaGetSymbolAddress((void**)&Ao, g_Ao);

    dim3 ggrid(D_MODEL / 128, MROWS / 128);   // (8, 64)

    gemm_bias_kernel<<<ggrid, 256>>>(q, Wq, bq, Qp, MROWS, D_MODEL, D_MODEL);
    gemm_bias_kernel<<<ggrid, 256>>>(k, Wk, bk, Kp, MROWS, D_MODEL, D_MODEL);
    gemm_bias_kernel<<<ggrid, 256>>>(v, Wv, bv, Vp, MROWS, D_MODEL, D_MODEL);

    const int nchunks = MROWS * NHEADS;       // 131072
    l2norm_kernel<<<nchunks / 8, 256>>>(Qp, nchunks);
    l2norm_kernel<<<nchunks / 8, 256>>>(Kp, nchunks);

    attn_kernel<<<dim3(SEQLEN / 64, BATCH * NHEADS), 256>>>(Qp, Kp, Vp, Ao);

    gemm_bias_kernel<<<ggrid, 256>>>(Ao, Wo, bo, out, MROWS, D_MODEL, D_MODEL);
}